// round 1
// baseline (speedup 1.0000x reference)
#include <cuda_runtime.h>
#include <math.h>

#define NSB    2050   // padded sequence (S = L + w - 1)
#define LOUT   2048
#define HD     128
#define NBATCH 32
#define BM     128
#define BN     128
#define BK     16
#define TM     8
#define TN     8
#define SPAD   132    // smem row stride (padded to break bank conflicts)

// Scratch (allocation-free rule: __device__ globals)
__device__ float g_sq0[NBATCH * NSB];
__device__ float g_sq1[NBATCH * NSB];
__device__ float g_r[NBATCH * NSB];
__device__ float g_c[NBATCH * NSB];

// ---------------------------------------------------------------------------
// Kernel 1: per-row squared norms of x0 / x1, and zero the r/c accumulators.
// ---------------------------------------------------------------------------
__global__ void prep_kernel(const float* __restrict__ x0,
                            const float* __restrict__ x1) {
    int idx = blockIdx.x * blockDim.x + threadIdx.x;
    if (idx >= NBATCH * NSB) return;
    const float4* a4 = (const float4*)(x0) + (size_t)idx * (HD / 4);
    const float4* b4 = (const float4*)(x1) + (size_t)idx * (HD / 4);
    float s0 = 0.f, s1 = 0.f;
#pragma unroll
    for (int i = 0; i < HD / 4; i++) {
        float4 va = a4[i];
        s0 += va.x * va.x + va.y * va.y + va.z * va.z + va.w * va.w;
        float4 vb = b4[i];
        s1 += vb.x * vb.x + vb.y * vb.y + vb.z * vb.z + vb.w * vb.w;
    }
    g_sq0[idx] = s0;
    g_sq1[idx] = s1;
    g_r[idx] = 0.f;
    g_c[idx] = 0.f;
}

// ---------------------------------------------------------------------------
// Kernel 2: fused batched "distance-GEMM" + A = 1/(1+dist) + row/col sums.
// One CTA computes a 128x128 tile of A for one batch and accumulates partial
// row sums (-> g_c) and col sums (-> g_r) via shared-mem staging + atomics.
// A is never materialized in global memory.
// ---------------------------------------------------------------------------
__global__ __launch_bounds__(256, 2)
void dist_kernel(const float* __restrict__ x0,
                 const float* __restrict__ x1) {
    __shared__ __align__(16) float As[BK][SPAD];
    __shared__ __align__(16) float Bs[BK][SPAD];
    __shared__ float s_c[BM];
    __shared__ float s_r[BN];

    const int b   = blockIdx.z;
    const int i0  = blockIdx.y * BM;
    const int j0  = blockIdx.x * BN;
    const int tid = threadIdx.x;
    const int tx  = tid & 15;
    const int ty  = tid >> 4;

    const float* Ag = x0 + (size_t)b * NSB * HD;
    const float* Bg = x1 + (size_t)b * NSB * HD;

    // Loader mapping: thread handles rows r0 and r0+64, k-quad kq..kq+3
    const int r0 = tid >> 2;          // 0..63
    const int kq = (tid & 3) * 4;     // 0,4,8,12

    const int gi0 = i0 + r0, gi1 = i0 + r0 + 64;
    const int gj0 = j0 + r0, gj1 = j0 + r0 + 64;
    const bool vi0 = gi0 < NSB, vi1 = gi1 < NSB;
    const bool vj0 = gj0 < NSB, vj1 = gj1 < NSB;
    const float* pA0 = Ag + (size_t)(vi0 ? gi0 : 0) * HD + kq;
    const float* pA1 = Ag + (size_t)(vi1 ? gi1 : 0) * HD + kq;
    const float* pB0 = Bg + (size_t)(vj0 ? gj0 : 0) * HD + kq;
    const float* pB1 = Bg + (size_t)(vj1 ? gj1 : 0) * HD + kq;

    float acc[TM][TN];
#pragma unroll
    for (int u = 0; u < TM; u++)
#pragma unroll
        for (int v = 0; v < TN; v++) acc[u][v] = 0.f;

    const float4 z4 = make_float4(0.f, 0.f, 0.f, 0.f);
    float4 pa0, pa1, pb0, pb1;

    // prologue: load k-chunk 0
    pa0 = vi0 ? *(const float4*)(pA0) : z4;
    pa1 = vi1 ? *(const float4*)(pA1) : z4;
    pb0 = vj0 ? *(const float4*)(pB0) : z4;
    pb1 = vj1 ? *(const float4*)(pB1) : z4;
    {
        As[kq + 0][r0] = pa0.x; As[kq + 1][r0] = pa0.y;
        As[kq + 2][r0] = pa0.z; As[kq + 3][r0] = pa0.w;
        As[kq + 0][r0 + 64] = pa1.x; As[kq + 1][r0 + 64] = pa1.y;
        As[kq + 2][r0 + 64] = pa1.z; As[kq + 3][r0 + 64] = pa1.w;
        Bs[kq + 0][r0] = pb0.x; Bs[kq + 1][r0] = pb0.y;
        Bs[kq + 2][r0] = pb0.z; Bs[kq + 3][r0] = pb0.w;
        Bs[kq + 0][r0 + 64] = pb1.x; Bs[kq + 1][r0 + 64] = pb1.y;
        Bs[kq + 2][r0 + 64] = pb1.z; Bs[kq + 3][r0 + 64] = pb1.w;
    }
    __syncthreads();

#pragma unroll 1
    for (int c = 0; c < HD / BK; c++) {
        // prefetch next k-chunk to registers (overlaps with compute)
        if (c < HD / BK - 1) {
            int kb = (c + 1) * BK;
            pa0 = vi0 ? *(const float4*)(pA0 + kb) : z4;
            pa1 = vi1 ? *(const float4*)(pA1 + kb) : z4;
            pb0 = vj0 ? *(const float4*)(pB0 + kb) : z4;
            pb1 = vj1 ? *(const float4*)(pB1 + kb) : z4;
        }
#pragma unroll
        for (int k = 0; k < BK; k++) {
            float4 a0 = *(const float4*)&As[k][ty * TM];
            float4 a1 = *(const float4*)&As[k][ty * TM + 4];
            float4 b0 = *(const float4*)&Bs[k][tx * TN];
            float4 b1 = *(const float4*)&Bs[k][tx * TN + 4];
            float af[TM] = {a0.x, a0.y, a0.z, a0.w, a1.x, a1.y, a1.z, a1.w};
            float bf[TN] = {b0.x, b0.y, b0.z, b0.w, b1.x, b1.y, b1.z, b1.w};
#pragma unroll
            for (int u = 0; u < TM; u++)
#pragma unroll
                for (int v = 0; v < TN; v++)
                    acc[u][v] += af[u] * bf[v];
        }
        __syncthreads();
        if (c < HD / BK - 1) {
            As[kq + 0][r0] = pa0.x; As[kq + 1][r0] = pa0.y;
            As[kq + 2][r0] = pa0.z; As[kq + 3][r0] = pa0.w;
            As[kq + 0][r0 + 64] = pa1.x; As[kq + 1][r0 + 64] = pa1.y;
            As[kq + 2][r0 + 64] = pa1.z; As[kq + 3][r0 + 64] = pa1.w;
            Bs[kq + 0][r0] = pb0.x; Bs[kq + 1][r0] = pb0.y;
            Bs[kq + 2][r0] = pb0.z; Bs[kq + 3][r0] = pb0.w;
            Bs[kq + 0][r0 + 64] = pb1.x; Bs[kq + 1][r0 + 64] = pb1.y;
            Bs[kq + 2][r0 + 64] = pb1.z; Bs[kq + 3][r0 + 64] = pb1.w;
            __syncthreads();
        }
    }

    // ---- epilogue: d2 -> A -> partial row/col sums ----
    float sqi[TM], sqj[TN];
#pragma unroll
    for (int u = 0; u < TM; u++) {
        int gi = i0 + ty * TM + u;
        sqi[u] = (gi < NSB) ? g_sq0[b * NSB + gi] : 3e18f;  // poison pad rows
    }
#pragma unroll
    for (int v = 0; v < TN; v++) {
        int gj = j0 + tx * TN + v;
        sqj[v] = (gj < NSB) ? g_sq1[b * NSB + gj] : 3e18f;
    }

    float rsum[TM], csum[TN];
#pragma unroll
    for (int u = 0; u < TM; u++) rsum[u] = 0.f;
#pragma unroll
    for (int v = 0; v < TN; v++) csum[v] = 0.f;

#pragma unroll
    for (int u = 0; u < TM; u++) {
#pragma unroll
        for (int v = 0; v < TN; v++) {
            float d2 = fmaxf(sqi[u] + sqj[v] - 2.f * acc[u][v], 0.f);
            float Aij;
            if (d2 < 64.f) {
                // exact slow path (essentially never taken for this data)
                Aij = 1.f / (1.f + sqrtf(d2));
            } else {
                // u = 1/sqrt(d2) = 1/dist;  1/(1+t) = u - u^2 + u^3 - u^4  (err ~ u^5)
                float uu;
                asm("rsqrt.approx.f32 %0, %1;" : "=f"(uu) : "f"(d2));
                Aij = uu * (1.f - uu * (1.f - uu * (1.f - uu)));
            }
            rsum[u] += Aij;   // sum over j  -> c[i]
            csum[v] += Aij;   // sum over i  -> r[j]
        }
    }

    __syncthreads();
    if (tid < BM) s_c[tid] = 0.f;
    else          s_r[tid - BM] = 0.f;
    __syncthreads();

#pragma unroll
    for (int u = 0; u < TM; u++) atomicAdd(&s_c[ty * TM + u], rsum[u]);
#pragma unroll
    for (int v = 0; v < TN; v++) atomicAdd(&s_r[tx * TN + v], csum[v]);
    __syncthreads();

    if (tid < BM) {
        int gi = i0 + tid;
        if (gi < NSB) atomicAdd(&g_c[b * NSB + gi], s_c[tid]);
    } else {
        int gj = j0 + (tid - BM);
        if (gj < NSB) atomicAdd(&g_r[b * NSB + gj], s_r[tid - BM]);
    }
}

// ---------------------------------------------------------------------------
// Kernel 3: windowed weighted pooling.
//   out0[b,l,h] = sum_{s=l..l+2} r[b,s] * x0[b,s,h]
//   out1[b,l,h] = sum_{s=l..l+2} c[b,s] * x1[b,s,h]
// ---------------------------------------------------------------------------
__global__ void window_kernel(const float* __restrict__ x0,
                              const float* __restrict__ x1,
                              float* __restrict__ out) {
    int t = blockIdx.x * blockDim.x + threadIdx.x;
    const int H4 = HD / 4;                     // 32
    if (t >= NBATCH * LOUT * H4) return;
    int h4 = t & 31;
    int l  = (t >> 5) & (LOUT - 1);
    int b  = t >> 16;                          // / (LOUT*H4)

    const float4* x04 = (const float4*)x0;
    const float4* x14 = (const float4*)x1;
    float4 a0 = make_float4(0.f, 0.f, 0.f, 0.f);
    float4 a1 = make_float4(0.f, 0.f, 0.f, 0.f);
    size_t base = ((size_t)b * NSB + l) * H4 + h4;
#pragma unroll
    for (int s = 0; s < 3; s++) {
        float rw = g_r[b * NSB + l + s];
        float cw = g_c[b * NSB + l + s];
        float4 v0 = x04[base + (size_t)s * H4];
        float4 v1 = x14[base + (size_t)s * H4];
        a0.x += rw * v0.x; a0.y += rw * v0.y; a0.z += rw * v0.z; a0.w += rw * v0.w;
        a1.x += cw * v1.x; a1.y += cw * v1.y; a1.z += cw * v1.z; a1.w += cw * v1.w;
    }
    float4* o = (float4*)out;
    size_t obase = ((size_t)b * LOUT + l) * H4 + h4;
    o[obase] = a0;
    o[(size_t)NBATCH * LOUT * H4 + obase] = a1;
}

// ---------------------------------------------------------------------------
extern "C" void kernel_launch(void* const* d_in, const int* in_sizes, int n_in,
                              void* d_out, int out_size) {
    const float* x0 = (const float*)d_in[0];
    const float* x1 = (const float*)d_in[1];
    float* out = (float*)d_out;

    prep_kernel<<<(NBATCH * NSB + 255) / 256, 256>>>(x0, x1);

    dim3 grid((NSB + BN - 1) / BN, (NSB + BM - 1) / BM, NBATCH);  // 17 x 17 x 32
    dist_kernel<<<grid, 256>>>(x0, x1);

    window_kernel<<<(NBATCH * LOUT * (HD / 4) + 255) / 256, 256>>>(x0, x1, out);
}

// round 2
// speedup vs baseline: 3.2387x; 3.2387x over previous
#include <cuda_runtime.h>
#include <cuda_bf16.h>
#include <math.h>

#define NSB    2050          // real sequence (S = L + w - 1)
#define NP     2176          // padded to 17 * 128
#define LOUT   2048
#define HD     128
#define NBATCH 32
#define BM     128
#define BN     128
#define SROW   72            // smem row stride in bf16 (64 data + 8 pad) = 144B
#define POISON 3e18f

// Scratch (__device__ globals: allocation-free rule)
__device__ __align__(16) __nv_bfloat16 g_x0b[NBATCH * NP * HD];
__device__ __align__(16) __nv_bfloat16 g_x1b[NBATCH * NP * HD];
__device__ float g_sq0[NBATCH * NP];
__device__ float g_sq1[NBATCH * NP];
__device__ float g_r[NBATCH * NP];
__device__ float g_c[NBATCH * NP];

// ---------------------------------------------------------------------------
// Kernel 1: squared norms (fp32) + bf16 conversion, padded rows zero/poison.
// ---------------------------------------------------------------------------
__global__ void prep_kernel(const float* __restrict__ x0,
                            const float* __restrict__ x1) {
    int idx = blockIdx.x * blockDim.x + threadIdx.x;
    if (idx >= NBATCH * NP) return;
    int b = idx / NP;
    int s = idx - b * NP;
    g_r[idx] = 0.f;
    g_c[idx] = 0.f;

    __nv_bfloat162* o0 = (__nv_bfloat162*)(g_x0b + (size_t)idx * HD);
    __nv_bfloat162* o1 = (__nv_bfloat162*)(g_x1b + (size_t)idx * HD);

    if (s < NSB) {
        const float4* a4 = (const float4*)(x0 + ((size_t)b * NSB + s) * HD);
        const float4* b4 = (const float4*)(x1 + ((size_t)b * NSB + s) * HD);
        float s0 = 0.f, s1 = 0.f;
#pragma unroll
        for (int i = 0; i < HD / 4; i++) {
            float4 va = a4[i];
            s0 += va.x * va.x + va.y * va.y + va.z * va.z + va.w * va.w;
            o0[2 * i + 0] = __floats2bfloat162_rn(va.x, va.y);
            o0[2 * i + 1] = __floats2bfloat162_rn(va.z, va.w);
            float4 vb = b4[i];
            s1 += vb.x * vb.x + vb.y * vb.y + vb.z * vb.z + vb.w * vb.w;
            o1[2 * i + 0] = __floats2bfloat162_rn(vb.x, vb.y);
            o1[2 * i + 1] = __floats2bfloat162_rn(vb.z, vb.w);
        }
        g_sq0[idx] = s0;
        g_sq1[idx] = s1;
    } else {
        __nv_bfloat162 z2 = __floats2bfloat162_rn(0.f, 0.f);
#pragma unroll
        for (int i = 0; i < HD / 2; i++) { o0[i] = z2; o1[i] = z2; }
        g_sq0[idx] = POISON;   // pad rows -> dist huge -> A ~ 6e-10
        g_sq1[idx] = POISON;
    }
}

// ---------------------------------------------------------------------------
// Kernel 2: bf16 tensor-core distance GEMM fused with A = 1/(1+dist) and
// row/col sum reduction. 128x128 tile per CTA, 8 warps, warp tile 32x64.
// ---------------------------------------------------------------------------
__global__ __launch_bounds__(256, 2)
void dist_kernel() {
    __shared__ __align__(16) __nv_bfloat16 As[BM * SROW];
    __shared__ __align__(16) __nv_bfloat16 Bs[BN * SROW];
    __shared__ float s_c[BM];
    __shared__ float s_r[BN];

    const int b  = blockIdx.z;
    const int i0 = blockIdx.y * BM;
    const int j0 = blockIdx.x * BN;
    const int tid  = threadIdx.x;
    const int wid  = tid >> 5;
    const int lane = tid & 31;
    const int g  = lane >> 2;        // group id (rows / cols within fragment)
    const int tg = lane & 3;         // thread-in-group (k pairs / col pairs)
    const int wm = (wid & 3) * 32;   // warp M origin in tile
    const int wn = (wid >> 2) * 64;  // warp N origin in tile

    const uint4* gA = (const uint4*)(g_x0b + ((size_t)b * NP + i0) * HD);
    const uint4* gB = (const uint4*)(g_x1b + ((size_t)b * NP + j0) * HD);
    uint4* sA4 = (uint4*)As;         // 9 uint4 per smem row
    uint4* sB4 = (uint4*)Bs;

    float acc[2][8][4];
#pragma unroll
    for (int mi = 0; mi < 2; mi++)
#pragma unroll
        for (int ni = 0; ni < 8; ni++)
#pragma unroll
            for (int c = 0; c < 4; c++) acc[mi][ni][c] = 0.f;

#pragma unroll
    for (int ch = 0; ch < 2; ch++) {           // K chunks of 64
        // load 128 rows x 64 bf16 of A and B (8 uint4 per row)
#pragma unroll
        for (int i = 0; i < 4; i++) {
            int linear = i * 256 + tid;
            int row = linear >> 3, c4 = linear & 7;
            sA4[row * 9 + c4] = gA[row * 16 + ch * 8 + c4];
            sB4[row * 9 + c4] = gB[row * 16 + ch * 8 + c4];
        }
        __syncthreads();

#pragma unroll
        for (int ks = 0; ks < 4; ks++) {       // k-steps of 16
            const int k0 = ks * 16;
            unsigned a[2][4], bb[8][2];
#pragma unroll
            for (int mi = 0; mi < 2; mi++) {
                const __nv_bfloat16* r0 = As + (wm + mi * 16 + g) * SROW + k0 + 2 * tg;
                const __nv_bfloat16* r1 = As + (wm + mi * 16 + g + 8) * SROW + k0 + 2 * tg;
                a[mi][0] = *(const unsigned*)(r0);
                a[mi][1] = *(const unsigned*)(r1);
                a[mi][2] = *(const unsigned*)(r0 + 8);
                a[mi][3] = *(const unsigned*)(r1 + 8);
            }
#pragma unroll
            for (int ni = 0; ni < 8; ni++) {
                const __nv_bfloat16* rb = Bs + (wn + ni * 8 + g) * SROW + k0 + 2 * tg;
                bb[ni][0] = *(const unsigned*)(rb);
                bb[ni][1] = *(const unsigned*)(rb + 8);
            }
#pragma unroll
            for (int mi = 0; mi < 2; mi++)
#pragma unroll
                for (int ni = 0; ni < 8; ni++) {
                    float* c = acc[mi][ni];
                    asm volatile(
                        "mma.sync.aligned.m16n8k16.row.col.f32.bf16.bf16.f32 "
                        "{%0,%1,%2,%3}, {%4,%5,%6,%7}, {%8,%9}, {%0,%1,%2,%3};"
                        : "+f"(c[0]), "+f"(c[1]), "+f"(c[2]), "+f"(c[3])
                        : "r"(a[mi][0]), "r"(a[mi][1]), "r"(a[mi][2]), "r"(a[mi][3]),
                          "r"(bb[ni][0]), "r"(bb[ni][1]));
                }
        }
        __syncthreads();
    }

    // zero the reduction staging
    if (tid < BM) s_c[tid] = 0.f;
    else          s_r[tid - BM] = 0.f;

    // ---- epilogue: d2 -> A=1/(1+sqrt(d2)) (no MUFU) -> partial sums ----
    float sqi[4];     // rows wm + mi*16 + h*8 + g
#pragma unroll
    for (int mi = 0; mi < 2; mi++)
#pragma unroll
        for (int h = 0; h < 2; h++)
            sqi[mi * 2 + h] = g_sq0[(size_t)b * NP + i0 + wm + mi * 16 + h * 8 + g];
    float sqj[16];    // cols wn + ni*8 + 2*tg + e
#pragma unroll
    for (int ni = 0; ni < 8; ni++)
#pragma unroll
        for (int e = 0; e < 2; e++)
            sqj[ni * 2 + e] = g_sq1[(size_t)b * NP + j0 + wn + ni * 8 + 2 * tg + e];

    float rs[4] = {0.f, 0.f, 0.f, 0.f};
    float cs[16];
#pragma unroll
    for (int i = 0; i < 16; i++) cs[i] = 0.f;

#pragma unroll
    for (int mi = 0; mi < 2; mi++)
#pragma unroll
        for (int ni = 0; ni < 8; ni++)
#pragma unroll
            for (int c = 0; c < 4; c++) {
                int h = c >> 1, e = c & 1;
                float d2 = fmaxf(fmaf(acc[mi][ni][c], -2.f, sqi[mi * 2 + h] + sqj[ni * 2 + e]), 0.f);
                float Aij;
                if (d2 < 64.f) {
                    Aij = 1.f / (1.f + sqrtf(d2));   // rare exact path
                } else {
                    // bit-hack rsqrt + 2 Newton steps: u = 1/sqrt(d2) = 1/dist
                    float xh = 0.5f * d2;
                    float y = __int_as_float(0x5f3759df - (__float_as_int(d2) >> 1));
                    y = y * fmaf(-(xh * y), y, 1.5f);
                    y = y * fmaf(-(xh * y), y, 1.5f);
                    // 1/(1+t) = u - u^2 + u^3 - u^4, err ~ u^5
                    float t = fmaf(-y, 1.f - y, 1.f);        // 1 - y(1-y)
                    Aij = y * fmaf(-y, t, 1.f);              // y(1 - y*t)
                }
                rs[mi * 2 + h] += Aij;     // sum over cols -> c[i]
                cs[ni * 2 + e] += Aij;     // sum over rows -> r[j]
            }

    // row sums: reduce across tg (xor 1,2); lanes tg==0 write
#pragma unroll
    for (int i = 0; i < 4; i++) {
        rs[i] += __shfl_xor_sync(0xffffffffu, rs[i], 1);
        rs[i] += __shfl_xor_sync(0xffffffffu, rs[i], 2);
    }
    // col sums: reduce across g (xor 4,8,16); lanes g==0 write
#pragma unroll
    for (int i = 0; i < 16; i++) {
        cs[i] += __shfl_xor_sync(0xffffffffu, cs[i], 4);
        cs[i] += __shfl_xor_sync(0xffffffffu, cs[i], 8);
        cs[i] += __shfl_xor_sync(0xffffffffu, cs[i], 16);
    }
    __syncthreads();
    if (tg == 0) {
#pragma unroll
        for (int mi = 0; mi < 2; mi++)
#pragma unroll
            for (int h = 0; h < 2; h++)
                atomicAdd(&s_c[wm + mi * 16 + h * 8 + g], rs[mi * 2 + h]);
    }
    if (g == 0) {
#pragma unroll
        for (int ni = 0; ni < 8; ni++)
#pragma unroll
            for (int e = 0; e < 2; e++)
                atomicAdd(&s_r[wn + ni * 8 + 2 * tg + e], cs[ni * 2 + e]);
    }
    __syncthreads();

    if (tid < BM) atomicAdd(&g_c[(size_t)b * NP + i0 + tid], s_c[tid]);
    else          atomicAdd(&g_r[(size_t)b * NP + j0 + (tid - BM)], s_r[tid - BM]);
}

// ---------------------------------------------------------------------------
// Kernel 3: windowed weighted pooling.
// ---------------------------------------------------------------------------
__global__ void window_kernel(const float* __restrict__ x0,
                              const float* __restrict__ x1,
                              float* __restrict__ out) {
    int t = blockIdx.x * blockDim.x + threadIdx.x;
    const int H4 = HD / 4;
    if (t >= NBATCH * LOUT * H4) return;
    int h4 = t & 31;
    int l  = (t >> 5) & (LOUT - 1);
    int b  = t >> 16;

    const float4* x04 = (const float4*)x0;
    const float4* x14 = (const float4*)x1;
    float4 a0 = make_float4(0.f, 0.f, 0.f, 0.f);
    float4 a1 = make_float4(0.f, 0.f, 0.f, 0.f);
    size_t base = ((size_t)b * NSB + l) * H4 + h4;
#pragma unroll
    for (int s = 0; s < 3; s++) {
        float rw = g_r[(size_t)b * NP + l + s];
        float cw = g_c[(size_t)b * NP + l + s];
        float4 v0 = x04[base + (size_t)s * H4];
        float4 v1 = x14[base + (size_t)s * H4];
        a0.x += rw * v0.x; a0.y += rw * v0.y; a0.z += rw * v0.z; a0.w += rw * v0.w;
        a1.x += cw * v1.x; a1.y += cw * v1.y; a1.z += cw * v1.z; a1.w += cw * v1.w;
    }
    float4* o = (float4*)out;
    size_t obase = ((size_t)b * LOUT + l) * H4 + h4;
    o[obase] = a0;
    o[(size_t)NBATCH * LOUT * H4 + obase] = a1;
}

// ---------------------------------------------------------------------------
extern "C" void kernel_launch(void* const* d_in, const int* in_sizes, int n_in,
                              void* d_out, int out_size) {
    const float* x0 = (const float*)d_in[0];
    const float* x1 = (const float*)d_in[1];
    float* out = (float*)d_out;

    prep_kernel<<<(NBATCH * NP + 255) / 256, 256>>>(x0, x1);

    dim3 grid(NP / BN, NP / BM, NBATCH);   // 17 x 17 x 32
    dist_kernel<<<grid, 256>>>();

    window_kernel<<<(NBATCH * LOUT * (HD / 4) + 255) / 256, 256>>>(x0, x1, out);
}

// round 4
// speedup vs baseline: 3.7069x; 1.1446x over previous
#include <cuda_runtime.h>
#include <cuda_bf16.h>
#include <math.h>
#include <stdint.h>

#define NSB    2050          // real sequence (S = L + w - 1)
#define NP     2176          // padded to 17 * 128
#define LOUT   2048
#define HD     128
#define NBATCH 32
#define BM     128
#define BN     128
#define POISON 3e18f
#define SROWB  272           // smem row stride in BYTES (256 data + 16 pad)
#define SM_B_OFF  34816      // 128 * 272
#define SM_TOTAL  69632      // two tiles

// Scratch (__device__ globals: allocation-free rule)
__device__ __align__(16) __nv_bfloat16 g_x0b[NBATCH * NP * HD];
__device__ __align__(16) __nv_bfloat16 g_x1b[NBATCH * NP * HD];
__device__ float g_sq0[NBATCH * NP];
__device__ float g_sq1[NBATCH * NP];
__device__ float g_r[NBATCH * NP];
__device__ float g_c[NBATCH * NP];

__device__ __forceinline__ uint32_t smem_u32(const void* p) {
    uint32_t a;
    asm("{ .reg .u64 t; cvta.to.shared.u64 t, %1; cvt.u32.u64 %0, t; }"
        : "=r"(a) : "l"(p));
    return a;
}
__device__ __forceinline__ void cp16(uint32_t dst, const void* src) {
    asm volatile("cp.async.cg.shared.global [%0], [%1], 16;"
                 :: "r"(dst), "l"(src));
}
__device__ __forceinline__ void ldsm_x4(uint32_t a, uint32_t& r0, uint32_t& r1,
                                        uint32_t& r2, uint32_t& r3) {
    asm volatile("ldmatrix.sync.aligned.m8n8.x4.shared.b16 {%0,%1,%2,%3}, [%4];"
                 : "=r"(r0), "=r"(r1), "=r"(r2), "=r"(r3) : "r"(a));
}

// ---------------------------------------------------------------------------
// Kernel 1: warp-per-row squared norms + bf16 conversion (coalesced).
// ---------------------------------------------------------------------------
__global__ void prep_kernel(const float* __restrict__ x0,
                            const float* __restrict__ x1) {
    int gw   = (blockIdx.x * blockDim.x + threadIdx.x) >> 5;   // one warp per row
    int lane = threadIdx.x & 31;
    if (gw >= NBATCH * NP) return;
    int b = gw / NP;
    int s = gw - b * NP;
    if (lane == 0) { g_r[gw] = 0.f; g_c[gw] = 0.f; }

    uint2* o0 = (uint2*)(g_x0b + (size_t)gw * HD) + lane;
    uint2* o1 = (uint2*)(g_x1b + (size_t)gw * HD) + lane;

    if (s < NSB) {
        float4 v0 = ((const float4*)(x0 + ((size_t)b * NSB + s) * HD))[lane];
        float4 v1 = ((const float4*)(x1 + ((size_t)b * NSB + s) * HD))[lane];
        __nv_bfloat162 p0 = __floats2bfloat162_rn(v0.x, v0.y);
        __nv_bfloat162 p1 = __floats2bfloat162_rn(v0.z, v0.w);
        __nv_bfloat162 q0 = __floats2bfloat162_rn(v1.x, v1.y);
        __nv_bfloat162 q1 = __floats2bfloat162_rn(v1.z, v1.w);
        uint2 w0, w1;
        w0.x = *(uint32_t*)&p0; w0.y = *(uint32_t*)&p1;
        w1.x = *(uint32_t*)&q0; w1.y = *(uint32_t*)&q1;
        *o0 = w0; *o1 = w1;
        float p = v0.x * v0.x + v0.y * v0.y + v0.z * v0.z + v0.w * v0.w;
        float q = v1.x * v1.x + v1.y * v1.y + v1.z * v1.z + v1.w * v1.w;
#pragma unroll
        for (int d = 16; d >= 1; d >>= 1) {
            p += __shfl_xor_sync(0xffffffffu, p, d);
            q += __shfl_xor_sync(0xffffffffu, q, d);
        }
        if (lane == 0) { g_sq0[gw] = p; g_sq1[gw] = q; }
    } else {
        uint2 z = make_uint2(0u, 0u);
        *o0 = z; *o1 = z;
        if (lane == 0) { g_sq0[gw] = POISON; g_sq1[gw] = POISON; }
    }
}

// ---------------------------------------------------------------------------
// Kernel 2: bf16 mma.sync distance GEMM, K-resident smem, ldmatrix fragments,
// fused A = 1/(1+dist) epilogue + row/col reduction.
// 128x128 tile per CTA, 8 warps, warp tile 32x64.
// ---------------------------------------------------------------------------
__global__ __launch_bounds__(256, 2)
void dist_kernel() {
    extern __shared__ __align__(16) char smem[];
    __shared__ float s_c[BM];
    __shared__ float s_r[BN];

    const int b  = blockIdx.z;
    const int i0 = blockIdx.y * BM;
    const int j0 = blockIdx.x * BN;
    const int tid  = threadIdx.x;
    const int wid  = tid >> 5;
    const int lane = tid & 31;
    const int g  = lane >> 2;        // fragment row group
    const int tg = lane & 3;         // thread-in-group
    const int wm = (wid & 3) * 32;   // warp M origin
    const int wn = (wid >> 2) * 64;  // warp N origin

    const uint32_t sA = smem_u32(smem);
    const uint32_t sB = sA + SM_B_OFF;

    // ---- one-shot async load of both full tiles (128 rows x 256B) ----
    const uint4* gA = (const uint4*)(g_x0b + ((size_t)b * NP + i0) * HD);
    const uint4* gB = (const uint4*)(g_x1b + ((size_t)b * NP + j0) * HD);
#pragma unroll
    for (int i = 0; i < 8; i++) {
        int chunk = i * 256 + tid;          // 0..2047
        int row = chunk >> 4, c16 = chunk & 15;
        uint32_t doff = (uint32_t)(row * SROWB + c16 * 16);
        cp16(sA + doff, gA + row * 16 + c16);
        cp16(sB + doff, gB + row * 16 + c16);
    }
    asm volatile("cp.async.commit_group;" ::: "memory");

    // epilogue scalars (overlap with async copies)
    const size_t bNP = (size_t)b * NP;
    float sqi[4];
#pragma unroll
    for (int mi = 0; mi < 2; mi++)
#pragma unroll
        for (int h = 0; h < 2; h++)
            sqi[mi * 2 + h] = g_sq0[bNP + i0 + wm + mi * 16 + h * 8 + g];
    float sqj[16];
#pragma unroll
    for (int ni = 0; ni < 8; ni++)
#pragma unroll
        for (int e = 0; e < 2; e++)
            sqj[ni * 2 + e] = g_sq1[bNP + j0 + wn + ni * 8 + 2 * tg + e];

    if (tid < BM) s_c[tid] = 0.f;
    else          s_r[tid - BM] = 0.f;

    asm volatile("cp.async.wait_group 0;" ::: "memory");
    __syncthreads();

    // ---- per-thread ldmatrix base offsets ----
    // A x4: lanes 0-7 m0-7@k0 | 8-15 m8-15@k0 | 16-23 m0-7@k+8 | 24-31 m8-15@k+8
    const uint32_t aBase = sA +
        (uint32_t)((wm + (lane & 7) + ((lane >> 3) & 1) * 8) * SROWB +
                   ((lane >> 4) & 1) * 16);
    // B x4: lanes 0-7 n0-7@k0 | 8-15 n0-7@k+8 | 16-23 n8-15@k0 | 24-31 n8-15@k+8
    const uint32_t bBase = sB +
        (uint32_t)((wn + (lane & 7) + ((lane >> 4) & 1) * 8) * SROWB +
                   ((lane >> 3) & 1) * 16);

    float acc[2][8][4];
#pragma unroll
    for (int mi = 0; mi < 2; mi++)
#pragma unroll
        for (int ni = 0; ni < 8; ni++)
#pragma unroll
            for (int c = 0; c < 4; c++) acc[mi][ni][c] = 0.f;

#pragma unroll
    for (int ks = 0; ks < 8; ks++) {
        const uint32_t kb = ks * 32;
        uint32_t a[2][4], bb[8][2];
#pragma unroll
        for (int mi = 0; mi < 2; mi++)
            ldsm_x4(aBase + mi * (16 * SROWB) + kb,
                    a[mi][0], a[mi][1], a[mi][2], a[mi][3]);
#pragma unroll
        for (int np = 0; np < 4; np++)
            ldsm_x4(bBase + np * (16 * SROWB) + kb,
                    bb[np * 2][0], bb[np * 2][1],
                    bb[np * 2 + 1][0], bb[np * 2 + 1][1]);
#pragma unroll
        for (int mi = 0; mi < 2; mi++)
#pragma unroll
            for (int ni = 0; ni < 8; ni++) {
                float* c = acc[mi][ni];
                asm volatile(
                    "mma.sync.aligned.m16n8k16.row.col.f32.bf16.bf16.f32 "
                    "{%0,%1,%2,%3}, {%4,%5,%6,%7}, {%8,%9}, {%0,%1,%2,%3};"
                    : "+f"(c[0]), "+f"(c[1]), "+f"(c[2]), "+f"(c[3])
                    : "r"(a[mi][0]), "r"(a[mi][1]), "r"(a[mi][2]), "r"(a[mi][3]),
                      "r"(bb[ni][0]), "r"(bb[ni][1]));
            }
    }

    // ---- epilogue: d2 -> A = 1/(1+dist) -> partial row/col sums ----
    float rs[4] = {0.f, 0.f, 0.f, 0.f};
    float cs[16];
#pragma unroll
    for (int i = 0; i < 16; i++) cs[i] = 0.f;

#pragma unroll
    for (int mi = 0; mi < 2; mi++)
#pragma unroll
        for (int ni = 0; ni < 8; ni++)
#pragma unroll
            for (int c = 0; c < 4; c++) {
                int h = c >> 1, e = c & 1;
                float d2 = fmaxf(fmaf(acc[mi][ni][c], -2.f,
                                      sqi[mi * 2 + h] + sqj[ni * 2 + e]), 0.f);
                float Aij;
                if (d2 < 64.f) {
                    Aij = 1.f / (1.f + sqrtf(d2));     // rare exact path
                } else {
                    float u;
                    asm("rsqrt.approx.f32 %0, %1;" : "=f"(u) : "f"(d2));
                    float t = fmaf(-u, 1.f - u, 1.f);  // 1 - u + u^2
                    Aij = u * fmaf(-u, t, 1.f);        // u - u^2 + u^3 - u^4
                }
                rs[mi * 2 + h] += Aij;
                cs[ni * 2 + e] += Aij;
            }

#pragma unroll
    for (int i = 0; i < 4; i++) {
        rs[i] += __shfl_xor_sync(0xffffffffu, rs[i], 1);
        rs[i] += __shfl_xor_sync(0xffffffffu, rs[i], 2);
    }
#pragma unroll
    for (int i = 0; i < 16; i++) {
        cs[i] += __shfl_xor_sync(0xffffffffu, cs[i], 4);
        cs[i] += __shfl_xor_sync(0xffffffffu, cs[i], 8);
        cs[i] += __shfl_xor_sync(0xffffffffu, cs[i], 16);
    }
    __syncthreads();
    if (tg == 0) {
#pragma unroll
        for (int mi = 0; mi < 2; mi++)
#pragma unroll
            for (int h = 0; h < 2; h++)
                atomicAdd(&s_c[wm + mi * 16 + h * 8 + g], rs[mi * 2 + h]);
    }
    if (g == 0) {
#pragma unroll
        for (int ni = 0; ni < 8; ni++)
#pragma unroll
            for (int e = 0; e < 2; e++)
                atomicAdd(&s_r[wn + ni * 8 + 2 * tg + e], cs[ni * 2 + e]);
    }
    __syncthreads();

    if (tid < BM) atomicAdd(&g_c[bNP + i0 + tid], s_c[tid]);
    else          atomicAdd(&g_r[bNP + j0 + (tid - BM)], s_r[tid - BM]);
}

// ---------------------------------------------------------------------------
// Kernel 3: windowed weighted pooling.
// ---------------------------------------------------------------------------
__global__ void window_kernel(const float* __restrict__ x0,
                              const float* __restrict__ x1,
                              float* __restrict__ out) {
    int t = blockIdx.x * blockDim.x + threadIdx.x;
    const int H4 = HD / 4;
    if (t >= NBATCH * LOUT * H4) return;
    int h4 = t & 31;
    int l  = (t >> 5) & (LOUT - 1);
    int b  = t >> 16;

    const float4* x04 = (const float4*)x0;
    const float4* x14 = (const float4*)x1;
    float4 a0 = make_float4(0.f, 0.f, 0.f, 0.f);
    float4 a1 = make_float4(0.f, 0.f, 0.f, 0.f);
    size_t base = ((size_t)b * NSB + l) * H4 + h4;
#pragma unroll
    for (int s = 0; s < 3; s++) {
        float rw = g_r[(size_t)b * NP + l + s];
        float cw = g_c[(size_t)b * NP + l + s];
        float4 v0 = x04[base + (size_t)s * H4];
        float4 v1 = x14[base + (size_t)s * H4];
        a0.x += rw * v0.x; a0.y += rw * v0.y; a0.z += rw * v0.z; a0.w += rw * v0.w;
        a1.x += cw * v1.x; a1.y += cw * v1.y; a1.z += cw * v1.z; a1.w += cw * v1.w;
    }
    float4* o = (float4*)out;
    size_t obase = ((size_t)b * LOUT + l) * H4 + h4;
    o[obase] = a0;
    o[(size_t)NBATCH * LOUT * H4 + obase] = a1;
}

// ---------------------------------------------------------------------------
extern "C" void kernel_launch(void* const* d_in, const int* in_sizes, int n_in,
                              void* d_out, int out_size) {
    const float* x0 = (const float*)d_in[0];
    const float* x1 = (const float*)d_in[1];
    float* out = (float*)d_out;

    cudaFuncSetAttribute(dist_kernel,
                         cudaFuncAttributeMaxDynamicSharedMemorySize, SM_TOTAL);

    prep_kernel<<<(NBATCH * NP * 32 + 255) / 256, 256>>>(x0, x1);

    dim3 grid(NP / BN, NP / BM, NBATCH);   // 17 x 17 x 32
    dist_kernel<<<grid, 256, SM_TOTAL>>>();

    window_kernel<<<(NBATCH * LOUT * (HD / 4) + 255) / 256, 256>>>(x0, x1, out);
}

// round 5
// speedup vs baseline: 3.9272x; 1.0594x over previous
#include <cuda_runtime.h>
#include <cuda_bf16.h>
#include <math.h>
#include <stdint.h>

#define NSB    2050          // real sequence (S = L + w - 1)
#define NP     2176          // padded to 17 * 128
#define LOUT   2048
#define HD     128
#define NBATCH 32
#define BM     128
#define BN     128
#define POISON 3e18f
#define TILE_BYTES 32768     // 128 rows x 256 B (contiguous, pre-swizzled)
#define SM_TOTAL   (1024 + 2 * TILE_BYTES)

// Scratch (__device__ globals: allocation-free rule).
// g_x0b/g_x1b hold bf16 rows PRE-SWIZZLED: within each 128-row block,
// 16B granule g of row r lives at granule (g ^ (r & 7)).
__device__ __align__(16) __nv_bfloat16 g_x0b[NBATCH * NP * HD];
__device__ __align__(16) __nv_bfloat16 g_x1b[NBATCH * NP * HD];
__device__ float g_sq0[NBATCH * NP];
__device__ float g_sq1[NBATCH * NP];
__device__ float g_r[NBATCH * NP];
__device__ float g_c[NBATCH * NP];

__device__ __forceinline__ uint32_t smem_u32(const void* p) {
    uint32_t a;
    asm("{ .reg .u64 t; cvta.to.shared.u64 t, %1; cvt.u32.u64 %0, t; }"
        : "=r"(a) : "l"(p));
    return a;
}
__device__ __forceinline__ void ldsm_x4(uint32_t a, uint32_t& r0, uint32_t& r1,
                                        uint32_t& r2, uint32_t& r3) {
    asm volatile("ldmatrix.sync.aligned.m8n8.x4.shared.b16 {%0,%1,%2,%3}, [%4];"
                 : "=r"(r0), "=r"(r1), "=r"(r2), "=r"(r3) : "r"(a));
}
#define MBAR_INIT(a, c) \
    asm volatile("mbarrier.init.shared.b64 [%0], %1;" :: "r"(a), "r"((uint32_t)(c)) : "memory")
#define MBAR_EXPECT_TX(a, n) \
    asm volatile("mbarrier.arrive.expect_tx.shared.b64 _, [%0], %1;" \
                 :: "r"(a), "r"((uint32_t)(n)) : "memory")
#define BULK_G2S(dst, src, n, mbar) \
    asm volatile("cp.async.bulk.shared::cluster.global.mbarrier::complete_tx::bytes " \
                 "[%0], [%1], %2, [%3];" \
                 :: "r"(dst), "l"(src), "r"((uint32_t)(n)), "r"(mbar) : "memory")
#define MBAR_WAIT(addr, par) do {                                              \
    uint32_t _m = (addr), _p = (par), _d;                                      \
    asm volatile("{ .reg .pred p; mbarrier.try_wait.parity.acquire.cta.shared::cta.b64 p, [%1], %2; selp.b32 %0,1,0,p; }" \
                 : "=r"(_d) : "r"(_m), "r"(_p) : "memory");                    \
    if (!_d) {                                                                 \
        asm volatile("{ .reg .pred P1; WL%=: mbarrier.try_wait.parity.acquire.cta.shared::cta.b64 P1, [%0], %1, 0x989680; @P1 bra.uni WD%=; bra.uni WL%=; WD%=: }" \
                     :: "r"(_m), "r"(_p) : "memory");                          \
    } } while (0)

// ---------------------------------------------------------------------------
// Kernel 1: warp-per-row squared norms + bf16 conversion, SWIZZLED output.
// ---------------------------------------------------------------------------
__global__ void prep_kernel(const float* __restrict__ x0,
                            const float* __restrict__ x1) {
    int gw   = (blockIdx.x * blockDim.x + threadIdx.x) >> 5;   // one warp per row
    int lane = threadIdx.x & 31;
    if (gw >= NBATCH * NP) return;
    int b = gw / NP;
    int s = gw - b * NP;
    if (lane == 0) { g_r[gw] = 0.f; g_c[gw] = 0.f; }

    // swizzled 8B slot for this lane within the row
    uint32_t boff = (uint32_t)((((lane >> 1) ^ (s & 7)) << 4) + (lane & 1) * 8);
    char* r0 = (char*)(g_x0b + (size_t)gw * HD) + boff;
    char* r1 = (char*)(g_x1b + (size_t)gw * HD) + boff;

    if (s < NSB) {
        float4 v0 = ((const float4*)(x0 + ((size_t)b * NSB + s) * HD))[lane];
        float4 v1 = ((const float4*)(x1 + ((size_t)b * NSB + s) * HD))[lane];
        __nv_bfloat162 p0 = __floats2bfloat162_rn(v0.x, v0.y);
        __nv_bfloat162 p1 = __floats2bfloat162_rn(v0.z, v0.w);
        __nv_bfloat162 q0 = __floats2bfloat162_rn(v1.x, v1.y);
        __nv_bfloat162 q1 = __floats2bfloat162_rn(v1.z, v1.w);
        uint2 w0, w1;
        w0.x = *(uint32_t*)&p0; w0.y = *(uint32_t*)&p1;
        w1.x = *(uint32_t*)&q0; w1.y = *(uint32_t*)&q1;
        *(uint2*)r0 = w0; *(uint2*)r1 = w1;
        float p = v0.x * v0.x + v0.y * v0.y + v0.z * v0.z + v0.w * v0.w;
        float q = v1.x * v1.x + v1.y * v1.y + v1.z * v1.z + v1.w * v1.w;
#pragma unroll
        for (int d = 16; d >= 1; d >>= 1) {
            p += __shfl_xor_sync(0xffffffffu, p, d);
            q += __shfl_xor_sync(0xffffffffu, q, d);
        }
        if (lane == 0) { g_sq0[gw] = p; g_sq1[gw] = q; }
    } else {
        uint2 z = make_uint2(0u, 0u);
        *(uint2*)r0 = z; *(uint2*)r1 = z;
        if (lane == 0) { g_sq0[gw] = POISON; g_sq1[gw] = POISON; }
    }
}

// ---------------------------------------------------------------------------
// Kernel 2: bf16 mma.sync distance GEMM. Tiles arrive via TWO cp.async.bulk
// DMAs (no LSU issue cost); ldmatrix uses the pre-applied XOR swizzle.
// Fused A = 1/(1+dist) epilogue + row/col reduction.
// ---------------------------------------------------------------------------
__global__ __launch_bounds__(256, 2)
void dist_kernel() {
    extern __shared__ __align__(1024) char smem[];
    __shared__ float s_c[BM];
    __shared__ float s_r[BN];

    const int b  = blockIdx.z;
    const int i0 = blockIdx.y * BM;
    const int j0 = blockIdx.x * BN;
    const int tid  = threadIdx.x;
    const int wid  = tid >> 5;
    const int lane = tid & 31;
    const int g  = lane >> 2;        // fragment row group
    const int tg = lane & 3;         // thread-in-group
    const int wm = (wid & 3) * 32;   // warp M origin
    const int wn = (wid >> 2) * 64;  // warp N origin

    const uint32_t sbar = smem_u32(smem);          // mbarrier at offset 0
    const uint32_t sA = sbar + 1024;
    const uint32_t sB = sA + TILE_BYTES;

    if (tid == 0) MBAR_INIT(sbar, 1);
    __syncthreads();
    if (tid == 0) {
        MBAR_EXPECT_TX(sbar, 2 * TILE_BYTES);
        BULK_G2S(sA, (const char*)(g_x0b + ((size_t)b * NP + i0) * HD),
                 TILE_BYTES, sbar);
        BULK_G2S(sB, (const char*)(g_x1b + ((size_t)b * NP + j0) * HD),
                 TILE_BYTES, sbar);
    }

    // epilogue scalars (overlap with DMA)
    const size_t bNP = (size_t)b * NP;
    float sqi[4];
#pragma unroll
    for (int mi = 0; mi < 2; mi++)
#pragma unroll
        for (int h = 0; h < 2; h++)
            sqi[mi * 2 + h] = g_sq0[bNP + i0 + wm + mi * 16 + h * 8 + g];
    float sqj[16];
#pragma unroll
    for (int ni = 0; ni < 8; ni++)
#pragma unroll
        for (int e = 0; e < 2; e++)
            sqj[ni * 2 + e] = g_sq1[bNP + j0 + wn + ni * 8 + 2 * tg + e];

    if (tid < BM) s_c[tid] = 0.f;
    else          s_r[tid - BM] = 0.f;

    // ldmatrix bases (swizzle: granule ^= row & 7; here row&7 == lane&7)
    const int l7  = lane & 7;
    const int hiA = (lane >> 4) & 1;            // A: k-half select
    const int hiB = (lane >> 3) & 1;            // B: k-half select
    const uint32_t baseA = sA + (uint32_t)((wm + (lane & 7) + ((lane >> 3) & 1) * 8) << 8);
    const uint32_t baseB = sB + (uint32_t)((wn + (lane & 7) + ((lane >> 4) & 1) * 8) << 8);

    float acc[2][8][4];
#pragma unroll
    for (int mi = 0; mi < 2; mi++)
#pragma unroll
        for (int ni = 0; ni < 8; ni++)
#pragma unroll
            for (int c = 0; c < 4; c++) acc[mi][ni][c] = 0.f;

    MBAR_WAIT(sbar, 0);

#pragma unroll
    for (int ks = 0; ks < 8; ks++) {
        const uint32_t offA = (uint32_t)(((2 * ks + hiA) ^ l7) << 4);
        const uint32_t offB = (uint32_t)(((2 * ks + hiB) ^ l7) << 4);
        uint32_t a[2][4], bb[8][2];
#pragma unroll
        for (int mi = 0; mi < 2; mi++)
            ldsm_x4(baseA + mi * 4096 + offA,
                    a[mi][0], a[mi][1], a[mi][2], a[mi][3]);
#pragma unroll
        for (int np = 0; np < 4; np++)
            ldsm_x4(baseB + np * 4096 + offB,
                    bb[np * 2][0], bb[np * 2][1],
                    bb[np * 2 + 1][0], bb[np * 2 + 1][1]);
#pragma unroll
        for (int mi = 0; mi < 2; mi++)
#pragma unroll
            for (int ni = 0; ni < 8; ni++) {
                float* c = acc[mi][ni];
                asm volatile(
                    "mma.sync.aligned.m16n8k16.row.col.f32.bf16.bf16.f32 "
                    "{%0,%1,%2,%3}, {%4,%5,%6,%7}, {%8,%9}, {%0,%1,%2,%3};"
                    : "+f"(c[0]), "+f"(c[1]), "+f"(c[2]), "+f"(c[3])
                    : "r"(a[mi][0]), "r"(a[mi][1]), "r"(a[mi][2]), "r"(a[mi][3]),
                      "r"(bb[ni][0]), "r"(bb[ni][1]));
            }
    }

    // ---- epilogue: d2 -> A = 1/(1+dist) -> partial row/col sums ----
    float rs[4] = {0.f, 0.f, 0.f, 0.f};
    float cs[16];
#pragma unroll
    for (int i = 0; i < 16; i++) cs[i] = 0.f;

#pragma unroll
    for (int mi = 0; mi < 2; mi++)
#pragma unroll
        for (int ni = 0; ni < 8; ni++)
#pragma unroll
            for (int c = 0; c < 4; c++) {
                int h = c >> 1, e = c & 1;
                float d2 = fmaxf(fmaf(acc[mi][ni][c], -2.f,
                                      sqi[mi * 2 + h] + sqj[ni * 2 + e]), 0.f);
                float Aij;
                if (d2 < 64.f) {
                    Aij = 1.f / (1.f + sqrtf(d2));     // rare exact path
                } else {
                    float u;
                    asm("rsqrt.approx.f32 %0, %1;" : "=f"(u) : "f"(d2));
                    float t = fmaf(-u, 1.f - u, 1.f);  // 1 - u + u^2
                    Aij = u * fmaf(-u, t, 1.f);        // u - u^2 + u^3 - u^4
                }
                rs[mi * 2 + h] += Aij;
                cs[ni * 2 + e] += Aij;
            }

#pragma unroll
    for (int i = 0; i < 4; i++) {
        rs[i] += __shfl_xor_sync(0xffffffffu, rs[i], 1);
        rs[i] += __shfl_xor_sync(0xffffffffu, rs[i], 2);
    }
#pragma unroll
    for (int i = 0; i < 16; i++) {
        cs[i] += __shfl_xor_sync(0xffffffffu, cs[i], 4);
        cs[i] += __shfl_xor_sync(0xffffffffu, cs[i], 8);
        cs[i] += __shfl_xor_sync(0xffffffffu, cs[i], 16);
    }
    __syncthreads();
    if (tg == 0) {
#pragma unroll
        for (int mi = 0; mi < 2; mi++)
#pragma unroll
            for (int h = 0; h < 2; h++)
                atomicAdd(&s_c[wm + mi * 16 + h * 8 + g], rs[mi * 2 + h]);
    }
    if (g == 0) {
#pragma unroll
        for (int ni = 0; ni < 8; ni++)
#pragma unroll
            for (int e = 0; e < 2; e++)
                atomicAdd(&s_r[wn + ni * 8 + 2 * tg + e], cs[ni * 2 + e]);
    }
    __syncthreads();

    if (tid < BM) atomicAdd(&g_c[bNP + i0 + tid], s_c[tid]);
    else          atomicAdd(&g_r[bNP + j0 + (tid - BM)], s_r[tid - BM]);
}

// ---------------------------------------------------------------------------
// Kernel 3: windowed weighted pooling; 2 outputs per thread (row reuse).
// ---------------------------------------------------------------------------
__global__ void window_kernel(const float* __restrict__ x0,
                              const float* __restrict__ x1,
                              float* __restrict__ out) {
    int t = blockIdx.x * blockDim.x + threadIdx.x;
    const int H4 = HD / 4;
    if (t >= NBATCH * (LOUT / 2) * H4) return;
    int h4 = t & 31;
    int lp = (t >> 5) & (LOUT / 2 - 1);
    int b  = t >> 15;
    int l0 = lp * 2;

    const float4* x04 = (const float4*)x0;
    const float4* x14 = (const float4*)x1;
    size_t base = ((size_t)b * NSB + l0) * H4 + h4;

    float rw[4], cw[4];
    float4 v0[4], v1[4];
#pragma unroll
    for (int s = 0; s < 4; s++) {
        rw[s] = g_r[(size_t)b * NP + l0 + s];
        cw[s] = g_c[(size_t)b * NP + l0 + s];
        v0[s] = x04[base + (size_t)s * H4];
        v1[s] = x14[base + (size_t)s * H4];
    }

    float4* o = (float4*)out;
    size_t obase = ((size_t)b * LOUT + l0) * H4 + h4;
    const size_t O1 = (size_t)NBATCH * LOUT * H4;
#pragma unroll
    for (int q = 0; q < 2; q++) {
        float4 a0, a1;
        a0.x = rw[q] * v0[q].x; a0.y = rw[q] * v0[q].y;
        a0.z = rw[q] * v0[q].z; a0.w = rw[q] * v0[q].w;
        a1.x = cw[q] * v1[q].x; a1.y = cw[q] * v1[q].y;
        a1.z = cw[q] * v1[q].z; a1.w = cw[q] * v1[q].w;
#pragma unroll
        for (int s = 1; s < 3; s++) {
            a0.x += rw[q + s] * v0[q + s].x; a0.y += rw[q + s] * v0[q + s].y;
            a0.z += rw[q + s] * v0[q + s].z; a0.w += rw[q + s] * v0[q + s].w;
            a1.x += cw[q + s] * v1[q + s].x; a1.y += cw[q + s] * v1[q + s].y;
            a1.z += cw[q + s] * v1[q + s].z; a1.w += cw[q + s] * v1[q + s].w;
        }
        o[obase + (size_t)q * H4] = a0;
        o[O1 + obase + (size_t)q * H4] = a1;
    }
}

// ---------------------------------------------------------------------------
extern "C" void kernel_launch(void* const* d_in, const int* in_sizes, int n_in,
                              void* d_out, int out_size) {
    const float* x0 = (const float*)d_in[0];
    const float* x1 = (const float*)d_in[1];
    float* out = (float*)d_out;

    cudaFuncSetAttribute(dist_kernel,
                         cudaFuncAttributeMaxDynamicSharedMemorySize, SM_TOTAL);

    prep_kernel<<<(NBATCH * NP * 32 + 255) / 256, 256>>>(x0, x1);

    dim3 grid(NP / BN, NP / BM, NBATCH);   // 17 x 17 x 32
    dist_kernel<<<grid, 256, SM_TOTAL>>>();

    window_kernel<<<(NBATCH * (LOUT / 2) * (HD / 4) + 255) / 256, 256>>>(x0, x1, out);
}